// round 8
// baseline (speedup 1.0000x reference)
#include <cuda_runtime.h>
#include <stdint.h>

// ---------------------------------------------------------------------------
// BatchTopK: global top-(32*T) over masked [B,S,F], scatter relu'd winners,
// EMA threshold. TWO-launch pipeline (last-block-done tickets):
//   KMS  : fused stream — zero output, read eligible x once, warp-ballot
//          compaction of keys >= pivot(2.25), FINE 4096-bin histogram
//          (bin = (key-PIVOT)>>12, clamped). Last block suffix-scans the
//          histogram -> exact key window [klo,khi) + needb.
//   KSEL : grid pass over candidates: key>=khi -> scatter winner;
//          in [klo,khi) -> compact to cand3 (~dozens). Last block: exact
//          32-bit radix select among cand3, ties by lowest index, EMA
//          threshold, full state reset for next graph replay.
//          Dormant exact fallback in block 0 if pivot assumption failed.
// ---------------------------------------------------------------------------

#define NFB 4096
#define PIVOT_KEY 0xC0100000u   // f2key(2.25f)
#define KEY_ZERO  0x80000000u   // f2key(+0.0f)
#define CAP  (1u << 22)
#define CAP3 (1u << 16)
#define MAXTIE 4096
#define WBUF_CAP 96
#define WBUF_FLUSH 64
#define SEG 4                   // work items per token in KMS

__device__ unsigned g_hist[NFB];
__device__ unsigned g_klo = 0xFFFFFFFFu;   // boundary window [klo, khi)
__device__ unsigned g_khi = 0xFFFFFFFFu;
__device__ unsigned g_needb;
__device__ unsigned g_flag;
__device__ unsigned g_ncand;
__device__ unsigned g_ncand3;
__device__ unsigned g_minpos = 0xFFFFFFFFu;
__device__ unsigned g_done;
__device__ unsigned g_done2;
__device__ uint2    g_cand[CAP];
__device__ uint2    g_cand3[CAP3];

__device__ __forceinline__ unsigned f2key(unsigned u) {
    unsigned m = ((unsigned)((int)u >> 31)) | 0x80000000u;
    return u ^ m;
}
__device__ __forceinline__ float key2f(unsigned k) {
    unsigned u = (k & 0x80000000u) ? (k ^ 0x80000000u) : ~k;
    return __uint_as_float(u);
}
// inclusive suffix sum within warp (lane L gets sum of lanes L..31)
__device__ __forceinline__ unsigned warp_suffix_incl(unsigned v, int lane) {
#pragma unroll
    for (int off = 1; off < 32; off <<= 1) {
        unsigned u = __shfl_down_sync(0xFFFFFFFFu, v, off);
        if (lane + off < 32) v += u;
    }
    return v;
}

// ------------------------- KMS: fused zero + scan + compact + fine hist
// blockDim MUST be 256 (8 warps).
__global__ void kms_stream(const float* __restrict__ x,
                           const int* __restrict__ mask,
                           float* __restrict__ out, int T, int F,
                           unsigned ktot) {
    __shared__ unsigned shist[NFB];
    __shared__ uint2 wbuf[8][WBUF_CAP];
    __shared__ unsigned wc[8];
    __shared__ unsigned gbs, s_ticket;
    __shared__ unsigned wsum[8], wsuf[8];
    const int tid = threadIdx.x;
    const int lane = tid & 31;
    const int w = tid >> 5;
    for (int i = tid; i < NFB; i += blockDim.x) shist[i] = 0u;
    __syncthreads();

    const int f4 = F >> 2;
    const float4 z4 = make_float4(0.f, 0.f, 0.f, 0.f);
    unsigned cnt = 0u;   // warp-uniform count in wbuf[w]

#define KS_PUSH(VAL, GIDX, ACT) do {                                          \
    unsigned key = f2key(__float_as_uint(VAL));                               \
    bool is = (ACT) && (key >= PIVOT_KEY);                                    \
    unsigned bal = __ballot_sync(0xFFFFFFFFu, is);                            \
    if (bal) {                                                                \
        if (is) {                                                             \
            unsigned r = __popc(bal & ((1u << lane) - 1u));                   \
            wbuf[w][cnt + r] = make_uint2(key, (GIDX));                       \
            unsigned fb = (key - PIVOT_KEY) >> 12;                            \
            if (fb > (NFB - 1u)) fb = NFB - 1u;                               \
            atomicAdd(&shist[fb], 1u);                                        \
        }                                                                     \
        cnt += (unsigned)__popc(bal);                                         \
        if (cnt >= WBUF_FLUSH) {                                              \
            unsigned base;                                                    \
            if (lane == 0) base = atomicAdd(&g_ncand, cnt);                   \
            base = __shfl_sync(0xFFFFFFFFu, base, 0);                         \
            for (unsigned q = lane; q < cnt; q += 32u) {                      \
                unsigned p = base + q;                                        \
                if (p < CAP) g_cand[p] = wbuf[w][q];                          \
            }                                                                 \
            cnt = 0u;                                                         \
        }                                                                     \
    }                                                                         \
} while (0)

    const int nitems = T * SEG;
    for (int it = blockIdx.x; it < nitems; it += gridDim.x) {
        const int t = it / SEG;
        const int sg = it - t * SEG;
        const int s0 = (int)(((long long)sg * f4) / SEG);
        const int s1 = (int)(((long long)(sg + 1) * f4) / SEG);
        const int len = s1 - s0;
        const int per = len >> 3;
        const int ws = s0 + w * per;
        const int we = (w == 7) ? s1 : ws + per;

        float4* ot = (float4*)(out + (size_t)t * F);
        if (mask[t] == 0) {                      // masked: pure write stream
            for (int i = ws + lane; i < we; i += 32) ot[i] = z4;
            continue;
        }
        const float4* xt = (const float4*)(x + (size_t)t * F);
        const unsigned tbase = (unsigned)t * (unsigned)F;
        int i = ws;
        for (; i + 128 <= we; i += 128) {
            float4 v[4];
#pragma unroll
            for (int j = 0; j < 4; j++) v[j] = xt[i + j * 32 + lane];
#pragma unroll
            for (int j = 0; j < 4; j++) ot[i + j * 32 + lane] = z4;
#pragma unroll
            for (int j = 0; j < 4; j++) {
                const unsigned gb0 = tbase + (unsigned)((i + j * 32 + lane) << 2);
                KS_PUSH(v[j].x, gb0 + 0u, true);
                KS_PUSH(v[j].y, gb0 + 1u, true);
                KS_PUSH(v[j].z, gb0 + 2u, true);
                KS_PUSH(v[j].w, gb0 + 3u, true);
            }
        }
        for (; i < we; i += 32) {
            const int ii = i + lane;
            const bool a = ii < we;
            float4 v = a ? xt[ii] : z4;
            if (a) ot[ii] = z4;
            const unsigned gb0 = tbase + (unsigned)(ii << 2);
            KS_PUSH(v.x, gb0 + 0u, a);
            KS_PUSH(v.y, gb0 + 1u, a);
            KS_PUSH(v.z, gb0 + 2u, a);
            KS_PUSH(v.w, gb0 + 3u, a);
        }
    }
#undef KS_PUSH

    // block-combined flush of warp buffer remainders
    if (lane == 0) wc[w] = cnt;
    __syncthreads();
    if (tid == 0) {
        unsigned s = 0;
        for (int q = 0; q < 8; q++) { unsigned c = wc[q]; wc[q] = s; s += c; }
        gbs = s ? atomicAdd(&g_ncand, s) : 0u;
    }
    __syncthreads();
    {
        const unsigned base = gbs + wc[w];
        for (unsigned q = lane; q < cnt; q += 32u) {
            unsigned p = base + q;
            if (p < CAP) g_cand[p] = wbuf[w][q];
        }
    }
    __syncthreads();
    for (int i = tid; i < NFB; i += blockDim.x) {
        unsigned v = shist[i];
        if (v) atomicAdd(&g_hist[i], v);
    }

    // ---- last-block ticket: suffix-scan histogram -> [klo,khi) + needb ----
    __syncthreads();
    if (tid == 0) { __threadfence(); s_ticket = atomicAdd(&g_done, 1u); }
    __syncthreads();
    if (s_ticket != (unsigned)gridDim.x - 1u) return;

    unsigned nc = __ldcg(&g_ncand);
    if (nc < ktot || nc > CAP) { if (tid == 0) g_flag = 1u; return; }

    unsigned own[16]; unsigned tot = 0u;
#pragma unroll
    for (int j = 0; j < 16; j++) { own[j] = __ldcg(&g_hist[tid * 16 + j]); tot += own[j]; }
    unsigned wsufi = warp_suffix_incl(tot, lane);
    if (lane == 0) wsum[w] = wsufi;
    __syncthreads();
    if (tid == 0) {
        unsigned run = 0u;
        for (int q = 7; q >= 0; q--) { wsuf[q] = run; run += wsum[q]; }
    }
    __syncthreads();
    unsigned above = wsuf[w] + (wsufi - tot);   // strictly above this thread's 16 bins
    unsigned cum = above;
    for (int j = 15; j >= 0; j--) {
        cum += own[j];
        unsigned before = cum - own[j];
        if (cum >= ktot && before < ktot) {
            unsigned b = (unsigned)(tid * 16 + j);
            g_klo = PIVOT_KEY + (b << 12);
            g_khi = (b == NFB - 1u) ? 0xFFFFFFFFu : PIVOT_KEY + ((b + 1u) << 12);
            g_needb = ktot - before;
        }
    }
}

// -------- KSEL: split + last-block exact select + threshold + reset
__global__ void ksel(const float* __restrict__ x,
                     const int* __restrict__ mask,
                     const float* __restrict__ thr_in,
                     float* __restrict__ out,
                     int T, int F, unsigned ktot, int n, int out_size) {
    __shared__ unsigned h[256];
    __shared__ unsigned sh_fb[NFB];
    __shared__ unsigned s_ticket, s_sel, s_need, s_tiecnt, s_minpos;
    __shared__ unsigned tie_idx[MAXTIE];
    const int tid = threadIdx.x;
    const int bd = blockDim.x;
    const int lane = tid & 31;

    // =================== dormant exact fallback (block 0) ===================
    if (__ldcg(&g_flag)) {
        if (blockIdx.x != 0) return;
        const int f4 = F >> 2;
        unsigned ck = 0u, need4 = 0u;
        bool takeall = false;
        // L1: coarse hist (key>>20) of eligible
        for (int i = tid; i < NFB; i += bd) sh_fb[i] = 0u;
        __syncthreads();
        for (int t = 0; t < T; t++) {
            if (mask[t] == 0) continue;
            const float4* xt = (const float4*)(x + (size_t)t * F);
            for (int i = tid; i < f4; i += bd) {
                float4 v = xt[i];
                atomicAdd(&sh_fb[f2key(__float_as_uint(v.x)) >> 20], 1u);
                atomicAdd(&sh_fb[f2key(__float_as_uint(v.y)) >> 20], 1u);
                atomicAdd(&sh_fb[f2key(__float_as_uint(v.z)) >> 20], 1u);
                atomicAdd(&sh_fb[f2key(__float_as_uint(v.w)) >> 20], 1u);
            }
        }
        __syncthreads();
        __shared__ unsigned s_lvl, s_ndl; __shared__ int s_ta;
        if (tid == 0) {
            unsigned cum = 0u; int b1 = -1; unsigned need = 0u;
            for (int d = NFB - 1; d >= 0; d--) {
                cum += sh_fb[d];
                if (cum >= ktot) { b1 = d; need = ktot - (cum - sh_fb[d]); break; }
            }
            s_ta = (b1 < 0) ? 1 : 0;
            s_lvl = (b1 < 0) ? 0u : (unsigned)b1;
            s_ndl = need;
        }
        __syncthreads();
        takeall = (s_ta != 0);
        if (!takeall) {
            // iterative narrowing: levels shift 12 then 4 then 0 over 20 low bits
            unsigned prefix = s_lvl << 20;      // known high bits
            unsigned pmask = 0xFFF00000u;
            unsigned need = s_ndl;
            const int shifts[3] = {12, 4, 0};
            const unsigned widths[3] = {256u, 256u, 16u};
            for (int lev = 0; lev < 3; lev++) {
                const int sh = shifts[lev];
                const unsigned wdt = widths[lev];
                for (unsigned d = tid; d < wdt; d += bd) h[d] = 0u;
                __syncthreads();
                for (int t = 0; t < T; t++) {
                    if (mask[t] == 0) continue;
                    const float4* xt = (const float4*)(x + (size_t)t * F);
                    for (int i = tid; i < f4; i += bd) {
                        float4 v = xt[i];
                        const float* vp = (const float*)&v;
#pragma unroll
                        for (int e = 0; e < 4; e++) {
                            unsigned key = f2key(__float_as_uint(vp[e]));
                            if ((key & pmask) == prefix)
                                atomicAdd(&h[(key >> sh) & (wdt - 1u)], 1u);
                        }
                    }
                }
                __syncthreads();
                if (tid == 0) {
                    unsigned cum = 0u; s_sel = 0u; s_need = need;
                    for (int d = (int)wdt - 1; d >= 0; d--) {
                        cum += h[d];
                        if (cum >= need) { s_sel = (unsigned)d; s_need = need - (cum - h[d]); break; }
                    }
                }
                __syncthreads();
                prefix |= s_sel << sh;
                pmask |= (wdt - 1u) << sh;
                need = s_need;
                __syncthreads();
            }
            ck = prefix; need4 = need;
        }
        // L4: final scatter pass + ties + minpos
        if (tid == 0) { s_tiecnt = 0u; s_minpos = 0xFFFFFFFFu; }
        __syncthreads();
        unsigned lmin = 0xFFFFFFFFu;
        for (int t = 0; t < T; t++) {
            if (mask[t] == 0) continue;
            const float4* xt = (const float4*)(x + (size_t)t * F);
            const unsigned tbase = (unsigned)t * (unsigned)F;
            for (int i = tid; i < f4; i += bd) {
                float4 v = xt[i];
                const unsigned gb0 = tbase + ((unsigned)i << 2);
                const float* vp = (const float*)&v;
#pragma unroll
                for (int e = 0; e < 4; e++) {
                    unsigned key = f2key(__float_as_uint(vp[e]));
                    if (takeall || key > ck) {
                        out[gb0 + e] = fmaxf(vp[e], 0.f);
                        if (key > KEY_ZERO) lmin = min(lmin, key);
                    } else if (key == ck && !takeall) {
                        unsigned p = atomicAdd(&s_tiecnt, 1u);
                        if (p < MAXTIE) tie_idx[p] = gb0 + (unsigned)e;
                    }
                }
            }
        }
        atomicMin(&s_minpos, lmin);
        __syncthreads();
        const unsigned tcnt = min(s_tiecnt, (unsigned)MAXTIE);
        const float cv = fmaxf(key2f(ck), 0.f);
        for (unsigned i = tid; i < tcnt; i += bd) {
            unsigned mi = tie_idx[i];
            unsigned rank = 0u;
            for (unsigned j = 0; j < tcnt; j++) rank += (tie_idx[j] < mi) ? 1u : 0u;
            if (rank < need4) out[mi] = cv;
        }
        __syncthreads();
        if (tid == 0) {
            unsigned mp = s_minpos;
            if (!takeall && need4 > 0u && ck > KEY_ZERO) mp = min(mp, ck);
            float thr = thr_in[0];
            float res = thr;
            if (mp != 0xFFFFFFFFu) res = 0.99f * thr + 0.01f * key2f(mp);
            out[out_size - 1] = res;
        }
        for (int i = n + tid; i < out_size - 1; i += bd) out[i] = 0.f;
        __syncthreads();
        for (int i = tid; i < NFB; i += bd) g_hist[i] = 0u;
        if (tid == 0) {
            g_klo = 0xFFFFFFFFu; g_khi = 0xFFFFFFFFu; g_needb = 0u;
            g_flag = 0u; g_ncand = 0u; g_ncand3 = 0u;
            g_minpos = 0xFFFFFFFFu; g_done = 0u; g_done2 = 0u;
        }
        return;
    }

    // ============================ fast path ============================
    const unsigned klo = g_klo, khi = g_khi;
    const unsigned nc = min(g_ncand, CAP);
    const unsigned wstart = ((unsigned)blockIdx.x * blockDim.x + (unsigned)(tid - lane));
    const unsigned stride = (unsigned)blockDim.x * gridDim.x;
    unsigned lmin = 0xFFFFFFFFu;

    for (unsigned base = wstart; base < nc; base += stride) {
        const unsigned i = base + lane;
        const bool valid = i < nc;
        uint2 c = valid ? g_cand[i] : make_uint2(0u, 0u);
        if (valid && c.x >= khi) {
            out[c.y] = fmaxf(key2f(c.x), 0.f);
            if (c.x > KEY_ZERO) lmin = min(lmin, c.x);
        }
        const bool isb = valid && c.x >= klo && c.x < khi;
        unsigned bal = __ballot_sync(0xFFFFFFFFu, isb);
        if (bal) {
            unsigned bse;
            if (lane == 0) bse = atomicAdd(&g_ncand3, (unsigned)__popc(bal));
            bse = __shfl_sync(0xFFFFFFFFu, bse, 0);
            if (isb) {
                unsigned r = __popc(bal & ((1u << lane) - 1u));
                unsigned p = bse + r;
                if (p < CAP3) g_cand3[p] = c;
            }
        }
    }
#pragma unroll
    for (int off = 16; off > 0; off >>= 1)
        lmin = min(lmin, __shfl_xor_sync(0xFFFFFFFFu, lmin, off));
    if (lane == 0 && lmin != 0xFFFFFFFFu) atomicMin(&g_minpos, lmin);

    // ---- last-block ticket: exact select among cand3 ----
    __syncthreads();
    if (tid == 0) { __threadfence(); s_ticket = atomicAdd(&g_done2, 1u); }
    __syncthreads();
    if (s_ticket != (unsigned)gridDim.x - 1u) return;

    const unsigned nc3 = min(__ldcg(&g_ncand3), (unsigned)CAP3);
    unsigned need = g_needb;
    unsigned ck = 0u, need4 = 0u;
    bool have = need > 0u && nc3 > 0u;

    if (have) {
        unsigned prefix = 0u, pmask = 0u;
        for (int sh = 24; sh >= 0; sh -= 8) {
            for (int d = tid; d < 256; d += bd) h[d] = 0u;
            __syncthreads();
            for (unsigned i = tid; i < nc3; i += bd) {
                unsigned key = __ldcg(&g_cand3[i].x);
                if ((key & pmask) == prefix) atomicAdd(&h[(key >> sh) & 255u], 1u);
            }
            __syncthreads();
            if (tid == 0) {
                unsigned cum = 0u; s_sel = 0u; s_need = need;
                for (int d = 255; d >= 0; d--) {
                    cum += h[d];
                    if (cum >= need) { s_sel = (unsigned)d; s_need = need - (cum - h[d]); break; }
                }
            }
            __syncthreads();
            prefix |= s_sel << sh;
            pmask |= 255u << sh;
            need = s_need;
            __syncthreads();
        }
        ck = prefix; need4 = need;

        if (tid == 0) { s_tiecnt = 0u; s_minpos = 0xFFFFFFFFu; }
        __syncthreads();
        unsigned lmin2 = 0xFFFFFFFFu;
        for (unsigned i = tid; i < nc3; i += bd) {
            unsigned key = __ldcg(&g_cand3[i].x);
            unsigned idx = __ldcg(&g_cand3[i].y);
            if (key > ck) {
                out[idx] = fmaxf(key2f(key), 0.f);
                if (key > KEY_ZERO) lmin2 = min(lmin2, key);
            } else if (key == ck) {
                unsigned p = atomicAdd(&s_tiecnt, 1u);
                if (p < MAXTIE) tie_idx[p] = idx;
            }
        }
        atomicMin(&s_minpos, lmin2);
        __syncthreads();
        const unsigned tcnt = min(s_tiecnt, (unsigned)MAXTIE);
        const float cv = fmaxf(key2f(ck), 0.f);
        for (unsigned i = tid; i < tcnt; i += bd) {
            unsigned mi = tie_idx[i];
            unsigned rank = 0u;
            for (unsigned j = 0; j < tcnt; j++) rank += (tie_idx[j] < mi) ? 1u : 0u;
            if (rank < need4) out[mi] = cv;
        }
        __syncthreads();
    }

    if (tid == 0) {
        unsigned mp = min(__ldcg(&g_minpos), have ? s_minpos : 0xFFFFFFFFu);
        if (have && need4 > 0u && ck > KEY_ZERO) mp = min(mp, ck);
        float thr = thr_in[0];
        float res = thr;
        if (mp != 0xFFFFFFFFu) res = 0.99f * thr + 0.01f * key2f(mp);
        out[out_size - 1] = res;
    }
    for (int i = n + tid; i < out_size - 1; i += bd) out[i] = 0.f;

    // ------------- reset persistent state for next graph replay -------------
    __syncthreads();
    for (int i = tid; i < NFB; i += bd) g_hist[i] = 0u;
    if (tid == 0) {
        g_klo = 0xFFFFFFFFu; g_khi = 0xFFFFFFFFu; g_needb = 0u;
        g_flag = 0u; g_ncand = 0u; g_ncand3 = 0u;
        g_minpos = 0xFFFFFFFFu; g_done = 0u; g_done2 = 0u;
    }
}

// ---------------------------------------------------------------------------
extern "C" void kernel_launch(void* const* d_in, const int* in_sizes, int n_in,
                              void* d_out, int out_size) {
    const float* x = (const float*)d_in[0];
    const int* mask = (const int*)d_in[1];
    const float* thr = (const float*)d_in[2];
    float* out = (float*)d_out;

    const int n = in_sizes[0];
    const int T = in_sizes[1];
    const int F = n / T;
    const unsigned ktot = 32u * (unsigned)T;

    const int nitems = T * SEG;
    int gs = 152 * 8;
    if (gs > nitems) gs = nitems;

    kms_stream<<<gs, 256>>>(x, mask, out, T, F, ktot);
    ksel<<<128, 256>>>(x, mask, thr, out, T, F, ktot, n, out_size);
}

// round 9
// speedup vs baseline: 1.2308x; 1.2308x over previous
#include <cuda_runtime.h>
#include <stdint.h>

// ---------------------------------------------------------------------------
// BatchTopK: global top-(32*T) over masked [B,S,F], scatter relu'd winners,
// EMA threshold. TWO-launch pipeline (last-block-done tickets):
//   KMS  : fused stream — zero output, read eligible x once, warp-ballot
//          compaction of keys >= pivot(2.25), FINE 4096-bin histogram
//          (bin = (key-PIVOT)>>12, clamped). Last block suffix-scans the
//          histogram -> exact key window [klo,khi) + needb.
//   KSEL : grid pass over candidates: key>=khi -> scatter winner;
//          in [klo,khi) -> compact to cand3 (~dozens). Last block: exact
//          32-bit radix select among cand3 with PARALLEL per-level suffix
//          scans, ties by lowest index, EMA threshold, full state reset.
//          Dormant exact fallback in block 0 if pivot assumption failed.
// ---------------------------------------------------------------------------

#define NFB 4096
#define PIVOT_KEY 0xC0100000u   // f2key(2.25f)
#define KEY_ZERO  0x80000000u   // f2key(+0.0f)
#define CAP  (1u << 22)
#define CAP3 (1u << 16)
#define MAXTIE 4096
#define WBUF_CAP 96
#define WBUF_FLUSH 64
#define SEG 4                   // work items per token in KMS

__device__ unsigned g_hist[NFB];
__device__ unsigned g_klo = 0xFFFFFFFFu;   // boundary window [klo, khi)
__device__ unsigned g_khi = 0xFFFFFFFFu;
__device__ unsigned g_needb;
__device__ unsigned g_flag;
__device__ unsigned g_ncand;
__device__ unsigned g_ncand3;
__device__ unsigned g_minpos = 0xFFFFFFFFu;
__device__ unsigned g_done;
__device__ unsigned g_done2;
__device__ uint2    g_cand[CAP];
__device__ uint2    g_cand3[CAP3];

__device__ __forceinline__ unsigned f2key(unsigned u) {
    unsigned m = ((unsigned)((int)u >> 31)) | 0x80000000u;
    return u ^ m;
}
__device__ __forceinline__ float key2f(unsigned k) {
    unsigned u = (k & 0x80000000u) ? (k ^ 0x80000000u) : ~k;
    return __uint_as_float(u);
}
// inclusive suffix sum within warp (lane L gets sum of lanes L..31)
__device__ __forceinline__ unsigned warp_suffix_incl(unsigned v, int lane) {
#pragma unroll
    for (int off = 1; off < 32; off <<= 1) {
        unsigned u = __shfl_down_sync(0xFFFFFFFFu, v, off);
        if (lane + off < 32) v += u;
    }
    return v;
}

// ------------------------- KMS: fused zero + scan + compact + fine hist
// blockDim MUST be 256 (8 warps).
__global__ void kms_stream(const float* __restrict__ x,
                           const int* __restrict__ mask,
                           float* __restrict__ out, int T, int F,
                           unsigned ktot) {
    __shared__ unsigned shist[NFB];
    __shared__ uint2 wbuf[8][WBUF_CAP];
    __shared__ unsigned wc[8];
    __shared__ unsigned gbs, s_ticket;
    __shared__ unsigned wsum[8], wsuf[8];
    const int tid = threadIdx.x;
    const int lane = tid & 31;
    const int w = tid >> 5;
    for (int i = tid; i < NFB; i += blockDim.x) shist[i] = 0u;
    __syncthreads();

    const int f4 = F >> 2;
    const float4 z4 = make_float4(0.f, 0.f, 0.f, 0.f);
    unsigned cnt = 0u;   // warp-uniform count in wbuf[w]

#define KS_PUSH(VAL, GIDX, ACT) do {                                          \
    unsigned key = f2key(__float_as_uint(VAL));                               \
    bool is = (ACT) && (key >= PIVOT_KEY);                                    \
    unsigned bal = __ballot_sync(0xFFFFFFFFu, is);                            \
    if (bal) {                                                                \
        if (is) {                                                             \
            unsigned r = __popc(bal & ((1u << lane) - 1u));                   \
            wbuf[w][cnt + r] = make_uint2(key, (GIDX));                       \
            unsigned fb = (key - PIVOT_KEY) >> 12;                            \
            if (fb > (NFB - 1u)) fb = NFB - 1u;                               \
            atomicAdd(&shist[fb], 1u);                                        \
        }                                                                     \
        cnt += (unsigned)__popc(bal);                                         \
        if (cnt >= WBUF_FLUSH) {                                              \
            unsigned base;                                                    \
            if (lane == 0) base = atomicAdd(&g_ncand, cnt);                   \
            base = __shfl_sync(0xFFFFFFFFu, base, 0);                         \
            for (unsigned q = lane; q < cnt; q += 32u) {                      \
                unsigned p = base + q;                                        \
                if (p < CAP) g_cand[p] = wbuf[w][q];                          \
            }                                                                 \
            cnt = 0u;                                                         \
        }                                                                     \
    }                                                                         \
} while (0)

    const int nitems = T * SEG;
    for (int it = blockIdx.x; it < nitems; it += gridDim.x) {
        const int t = it / SEG;
        const int sg = it - t * SEG;
        const int s0 = (int)(((long long)sg * f4) / SEG);
        const int s1 = (int)(((long long)(sg + 1) * f4) / SEG);
        const int len = s1 - s0;
        const int per = len >> 3;
        const int ws = s0 + w * per;
        const int we = (w == 7) ? s1 : ws + per;

        float4* ot = (float4*)(out + (size_t)t * F);
        if (mask[t] == 0) {                      // masked: pure write stream
            for (int i = ws + lane; i < we; i += 32) ot[i] = z4;
            continue;
        }
        const float4* xt = (const float4*)(x + (size_t)t * F);
        const unsigned tbase = (unsigned)t * (unsigned)F;
        int i = ws;
        for (; i + 128 <= we; i += 128) {
            float4 v[4];
#pragma unroll
            for (int j = 0; j < 4; j++) v[j] = xt[i + j * 32 + lane];
#pragma unroll
            for (int j = 0; j < 4; j++) ot[i + j * 32 + lane] = z4;
#pragma unroll
            for (int j = 0; j < 4; j++) {
                const unsigned gb0 = tbase + (unsigned)((i + j * 32 + lane) << 2);
                KS_PUSH(v[j].x, gb0 + 0u, true);
                KS_PUSH(v[j].y, gb0 + 1u, true);
                KS_PUSH(v[j].z, gb0 + 2u, true);
                KS_PUSH(v[j].w, gb0 + 3u, true);
            }
        }
        for (; i < we; i += 32) {
            const int ii = i + lane;
            const bool a = ii < we;
            float4 v = a ? xt[ii] : z4;
            if (a) ot[ii] = z4;
            const unsigned gb0 = tbase + (unsigned)(ii << 2);
            KS_PUSH(v.x, gb0 + 0u, a);
            KS_PUSH(v.y, gb0 + 1u, a);
            KS_PUSH(v.z, gb0 + 2u, a);
            KS_PUSH(v.w, gb0 + 3u, a);
        }
    }
#undef KS_PUSH

    // block-combined flush of warp buffer remainders
    if (lane == 0) wc[w] = cnt;
    __syncthreads();
    if (tid == 0) {
        unsigned s = 0;
        for (int q = 0; q < 8; q++) { unsigned c = wc[q]; wc[q] = s; s += c; }
        gbs = s ? atomicAdd(&g_ncand, s) : 0u;
    }
    __syncthreads();
    {
        const unsigned base = gbs + wc[w];
        for (unsigned q = lane; q < cnt; q += 32u) {
            unsigned p = base + q;
            if (p < CAP) g_cand[p] = wbuf[w][q];
        }
    }
    __syncthreads();
    for (int i = tid; i < NFB; i += blockDim.x) {
        unsigned v = shist[i];
        if (v) atomicAdd(&g_hist[i], v);
    }

    // ---- last-block ticket: suffix-scan histogram -> [klo,khi) + needb ----
    __syncthreads();
    if (tid == 0) { __threadfence(); s_ticket = atomicAdd(&g_done, 1u); }
    __syncthreads();
    if (s_ticket != (unsigned)gridDim.x - 1u) return;

    unsigned nc = __ldcg(&g_ncand);
    if (nc < ktot || nc > CAP) { if (tid == 0) g_flag = 1u; return; }

    unsigned own[16]; unsigned tot = 0u;
#pragma unroll
    for (int j = 0; j < 16; j++) { own[j] = __ldcg(&g_hist[tid * 16 + j]); tot += own[j]; }
    unsigned wsufi = warp_suffix_incl(tot, lane);
    if (lane == 0) wsum[w] = wsufi;
    __syncthreads();
    if (tid == 0) {
        unsigned run = 0u;
        for (int q = 7; q >= 0; q--) { wsuf[q] = run; run += wsum[q]; }
    }
    __syncthreads();
    unsigned above = wsuf[w] + (wsufi - tot);   // strictly above this thread's 16 bins
    unsigned cum = above;
    for (int j = 15; j >= 0; j--) {
        cum += own[j];
        unsigned before = cum - own[j];
        if (cum >= ktot && before < ktot) {
            unsigned b = (unsigned)(tid * 16 + j);
            g_klo = PIVOT_KEY + (b << 12);
            g_khi = (b == NFB - 1u) ? 0xFFFFFFFFu : PIVOT_KEY + ((b + 1u) << 12);
            g_needb = ktot - before;
        }
    }
}

// -------- KSEL: split + last-block exact select + threshold + reset
// blockDim MUST be 256 (parallel scans assume 8 warps).
__global__ void ksel(const float* __restrict__ x,
                     const int* __restrict__ mask,
                     const float* __restrict__ thr_in,
                     float* __restrict__ out,
                     int T, int F, unsigned ktot, int n, int out_size) {
    __shared__ unsigned h[256];
    __shared__ unsigned sh_fb[NFB];
    __shared__ unsigned s_ticket, s_sel, s_need, s_tiecnt, s_minpos;
    __shared__ unsigned wsum[8], wsuf[8];
    __shared__ unsigned tie_idx[MAXTIE];
    const int tid = threadIdx.x;
    const int bd = blockDim.x;
    const int lane = tid & 31;
    const int w = tid >> 5;

    // =================== dormant exact fallback (block 0) ===================
    if (__ldcg(&g_flag)) {
        if (blockIdx.x != 0) return;
        const int f4 = F >> 2;
        unsigned ck = 0u, need4 = 0u;
        bool takeall = false;
        for (int i = tid; i < NFB; i += bd) sh_fb[i] = 0u;
        __syncthreads();
        for (int t = 0; t < T; t++) {
            if (mask[t] == 0) continue;
            const float4* xt = (const float4*)(x + (size_t)t * F);
            for (int i = tid; i < f4; i += bd) {
                float4 v = xt[i];
                atomicAdd(&sh_fb[f2key(__float_as_uint(v.x)) >> 20], 1u);
                atomicAdd(&sh_fb[f2key(__float_as_uint(v.y)) >> 20], 1u);
                atomicAdd(&sh_fb[f2key(__float_as_uint(v.z)) >> 20], 1u);
                atomicAdd(&sh_fb[f2key(__float_as_uint(v.w)) >> 20], 1u);
            }
        }
        __syncthreads();
        __shared__ unsigned s_lvl, s_ndl; __shared__ int s_ta;
        if (tid == 0) {
            unsigned cum = 0u; int b1 = -1; unsigned need = 0u;
            for (int d = NFB - 1; d >= 0; d--) {
                cum += sh_fb[d];
                if (cum >= ktot) { b1 = d; need = ktot - (cum - sh_fb[d]); break; }
            }
            s_ta = (b1 < 0) ? 1 : 0;
            s_lvl = (b1 < 0) ? 0u : (unsigned)b1;
            s_ndl = need;
        }
        __syncthreads();
        takeall = (s_ta != 0);
        if (!takeall) {
            unsigned prefix = s_lvl << 20;
            unsigned pmask = 0xFFF00000u;
            unsigned need = s_ndl;
            const int shifts[3] = {12, 4, 0};
            const unsigned widths[3] = {256u, 256u, 16u};
            for (int lev = 0; lev < 3; lev++) {
                const int sh = shifts[lev];
                const unsigned wdt = widths[lev];
                for (unsigned d = tid; d < wdt; d += bd) h[d] = 0u;
                __syncthreads();
                for (int t = 0; t < T; t++) {
                    if (mask[t] == 0) continue;
                    const float4* xt = (const float4*)(x + (size_t)t * F);
                    for (int i = tid; i < f4; i += bd) {
                        float4 v = xt[i];
                        const float* vp = (const float*)&v;
#pragma unroll
                        for (int e = 0; e < 4; e++) {
                            unsigned key = f2key(__float_as_uint(vp[e]));
                            if ((key & pmask) == prefix)
                                atomicAdd(&h[(key >> sh) & (wdt - 1u)], 1u);
                        }
                    }
                }
                __syncthreads();
                if (tid == 0) {
                    unsigned cum = 0u; s_sel = 0u; s_need = need;
                    for (int d = (int)wdt - 1; d >= 0; d--) {
                        cum += h[d];
                        if (cum >= need) { s_sel = (unsigned)d; s_need = need - (cum - h[d]); break; }
                    }
                }
                __syncthreads();
                prefix |= s_sel << sh;
                pmask |= (wdt - 1u) << sh;
                need = s_need;
                __syncthreads();
            }
            ck = prefix; need4 = need;
        }
        if (tid == 0) { s_tiecnt = 0u; s_minpos = 0xFFFFFFFFu; }
        __syncthreads();
        unsigned lmin = 0xFFFFFFFFu;
        for (int t = 0; t < T; t++) {
            if (mask[t] == 0) continue;
            const float4* xt = (const float4*)(x + (size_t)t * F);
            const unsigned tbase = (unsigned)t * (unsigned)F;
            for (int i = tid; i < f4; i += bd) {
                float4 v = xt[i];
                const unsigned gb0 = tbase + ((unsigned)i << 2);
                const float* vp = (const float*)&v;
#pragma unroll
                for (int e = 0; e < 4; e++) {
                    unsigned key = f2key(__float_as_uint(vp[e]));
                    if (takeall || key > ck) {
                        out[gb0 + e] = fmaxf(vp[e], 0.f);
                        if (key > KEY_ZERO) lmin = min(lmin, key);
                    } else if (key == ck && !takeall) {
                        unsigned p = atomicAdd(&s_tiecnt, 1u);
                        if (p < MAXTIE) tie_idx[p] = gb0 + (unsigned)e;
                    }
                }
            }
        }
        atomicMin(&s_minpos, lmin);
        __syncthreads();
        const unsigned tcnt = min(s_tiecnt, (unsigned)MAXTIE);
        const float cv = fmaxf(key2f(ck), 0.f);
        for (unsigned i = tid; i < tcnt; i += bd) {
            unsigned mi = tie_idx[i];
            unsigned rank = 0u;
            for (unsigned j = 0; j < tcnt; j++) rank += (tie_idx[j] < mi) ? 1u : 0u;
            if (rank < need4) out[mi] = cv;
        }
        __syncthreads();
        if (tid == 0) {
            unsigned mp = s_minpos;
            if (!takeall && need4 > 0u && ck > KEY_ZERO) mp = min(mp, ck);
            float thr = thr_in[0];
            float res = thr;
            if (mp != 0xFFFFFFFFu) res = 0.99f * thr + 0.01f * key2f(mp);
            out[out_size - 1] = res;
        }
        for (int i = n + tid; i < out_size - 1; i += bd) out[i] = 0.f;
        __syncthreads();
        for (int i = tid; i < NFB; i += bd) g_hist[i] = 0u;
        if (tid == 0) {
            g_klo = 0xFFFFFFFFu; g_khi = 0xFFFFFFFFu; g_needb = 0u;
            g_flag = 0u; g_ncand = 0u; g_ncand3 = 0u;
            g_minpos = 0xFFFFFFFFu; g_done = 0u; g_done2 = 0u;
        }
        return;
    }

    // ============================ fast path ============================
    const unsigned klo = g_klo, khi = g_khi;
    const unsigned nc = min(g_ncand, CAP);
    const unsigned wstart = ((unsigned)blockIdx.x * blockDim.x + (unsigned)(tid - lane));
    const unsigned stride = (unsigned)blockDim.x * gridDim.x;
    unsigned lmin = 0xFFFFFFFFu;

    for (unsigned base = wstart; base < nc; base += stride) {
        const unsigned i = base + lane;
        const bool valid = i < nc;
        uint2 c = valid ? g_cand[i] : make_uint2(0u, 0u);
        if (valid && c.x >= khi) {
            out[c.y] = fmaxf(key2f(c.x), 0.f);
            if (c.x > KEY_ZERO) lmin = min(lmin, c.x);
        }
        const bool isb = valid && c.x >= klo && c.x < khi;
        unsigned bal = __ballot_sync(0xFFFFFFFFu, isb);
        if (bal) {
            unsigned bse;
            if (lane == 0) bse = atomicAdd(&g_ncand3, (unsigned)__popc(bal));
            bse = __shfl_sync(0xFFFFFFFFu, bse, 0);
            if (isb) {
                unsigned r = __popc(bal & ((1u << lane) - 1u));
                unsigned p = bse + r;
                if (p < CAP3) g_cand3[p] = c;
            }
        }
    }
#pragma unroll
    for (int off = 16; off > 0; off >>= 1)
        lmin = min(lmin, __shfl_xor_sync(0xFFFFFFFFu, lmin, off));
    if (lane == 0 && lmin != 0xFFFFFFFFu) atomicMin(&g_minpos, lmin);

    // ---- last-block ticket: exact select among cand3 (PARALLEL scans) ----
    __syncthreads();
    if (tid == 0) { __threadfence(); s_ticket = atomicAdd(&g_done2, 1u); }
    __syncthreads();
    if (s_ticket != (unsigned)gridDim.x - 1u) return;

    const unsigned nc3 = min(__ldcg(&g_ncand3), (unsigned)CAP3);
    unsigned need = g_needb;
    unsigned ck = 0u, need4 = 0u;
    bool have = need > 0u && nc3 > 0u;

    if (have) {
        unsigned prefix = 0u, pmask = 0u;
        for (int sh = 24; sh >= 0; sh -= 8) {
            h[tid] = 0u;
            __syncthreads();
            for (unsigned i = tid; i < nc3; i += bd) {
                unsigned key = __ldcg(&g_cand3[i].x);
                if ((key & pmask) == prefix) atomicAdd(&h[(key >> sh) & 255u], 1u);
            }
            __syncthreads();
            // parallel suffix scan over 256 bins (tid == bin)
            {
                unsigned own = h[tid];
                unsigned wsufi = warp_suffix_incl(own, lane);
                if (lane == 0) wsum[w] = wsufi;
                __syncthreads();
                if (tid == 0) {
                    unsigned run = 0u;
                    for (int q = 7; q >= 0; q--) { wsuf[q] = run; run += wsum[q]; }
                }
                __syncthreads();
                unsigned incl = wsufi + wsuf[w];     // sum of bins >= tid
                unsigned above = incl - own;         // sum of bins >  tid
                if (own && above < need && incl >= need) {
                    s_sel = (unsigned)tid;
                    s_need = need - above;
                }
            }
            __syncthreads();
            prefix |= s_sel << sh;
            pmask |= 255u << sh;
            need = s_need;
            __syncthreads();
        }
        ck = prefix; need4 = need;

        if (tid == 0) { s_tiecnt = 0u; s_minpos = 0xFFFFFFFFu; }
        __syncthreads();
        unsigned lmin2 = 0xFFFFFFFFu;
        for (unsigned i = tid; i < nc3; i += bd) {
            unsigned key = __ldcg(&g_cand3[i].x);
            unsigned idx = __ldcg(&g_cand3[i].y);
            if (key > ck) {
                out[idx] = fmaxf(key2f(key), 0.f);
                if (key > KEY_ZERO) lmin2 = min(lmin2, key);
            } else if (key == ck) {
                unsigned p = atomicAdd(&s_tiecnt, 1u);
                if (p < MAXTIE) tie_idx[p] = idx;
            }
        }
        atomicMin(&s_minpos, lmin2);
        __syncthreads();
        const unsigned tcnt = min(s_tiecnt, (unsigned)MAXTIE);
        const float cv = fmaxf(key2f(ck), 0.f);
        for (unsigned i = tid; i < tcnt; i += bd) {
            unsigned mi = tie_idx[i];
            unsigned rank = 0u;
            for (unsigned j = 0; j < tcnt; j++) rank += (tie_idx[j] < mi) ? 1u : 0u;
            if (rank < need4) out[mi] = cv;
        }
        __syncthreads();
    }

    if (tid == 0) {
        unsigned mp = min(__ldcg(&g_minpos), have ? s_minpos : 0xFFFFFFFFu);
        if (have && need4 > 0u && ck > KEY_ZERO) mp = min(mp, ck);
        float thr = thr_in[0];
        float res = thr;
        if (mp != 0xFFFFFFFFu) res = 0.99f * thr + 0.01f * key2f(mp);
        out[out_size - 1] = res;
    }
    for (int i = n + tid; i < out_size - 1; i += bd) out[i] = 0.f;

    // ------------- reset persistent state for next graph replay -------------
    __syncthreads();
    for (int i = tid; i < NFB; i += bd) g_hist[i] = 0u;
    if (tid == 0) {
        g_klo = 0xFFFFFFFFu; g_khi = 0xFFFFFFFFu; g_needb = 0u;
        g_flag = 0u; g_ncand = 0u; g_ncand3 = 0u;
        g_minpos = 0xFFFFFFFFu; g_done = 0u; g_done2 = 0u;
    }
}

// ---------------------------------------------------------------------------
extern "C" void kernel_launch(void* const* d_in, const int* in_sizes, int n_in,
                              void* d_out, int out_size) {
    const float* x = (const float*)d_in[0];
    const int* mask = (const int*)d_in[1];
    const float* thr = (const float*)d_in[2];
    float* out = (float*)d_out;

    const int n = in_sizes[0];
    const int T = in_sizes[1];
    const int F = n / T;
    const unsigned ktot = 32u * (unsigned)T;

    const int nitems = T * SEG;
    int gs = 152 * 8;
    if (gs > nitems) gs = nitems;

    kms_stream<<<gs, 256>>>(x, mask, out, T, F, ktot);
    ksel<<<512, 256>>>(x, mask, thr, out, T, F, ktot, n, out_size);
}